// round 16
// baseline (speedup 1.0000x reference)
#include <cuda_runtime.h>
#include <math.h>
#include <stdint.h>

#define NTOK 65536
#define CIN 192
#define HID 384
#define OUTD 192
#define NE 8
#define KCAP 10240
#define TTILE 32
#define LSCALE 2.0f

// FFN smem (u32 units); X and H planes share one union; pair-interleaved rows
#define XW32   116
#define HW32   212
#define OFF_XL 3712      /* 32*116 */
#define OFF_HL 6784      /* 32*212 */
#define OFF_BW 13568
#define OFF_GW 13696
#define OFF_TOK 13728
#define FFN_U32 13760

// fragment-vector weight layouts (u32 per expert)
#define W1PE 43008       /* 14kt*4kq*8w*8g*6nj*2pr */
#define W2PE 53248       /* 26kt*4kq*8w*8g*4njpad*2pr */
#define A1PE 3072        /* 12kt*4kq*4nh*8g*2pr */
#define A2PE 6144        /* 24kt*4kq*4nh*8g*2pr */

typedef unsigned long long ull;

__device__ __forceinline__ unsigned short f2bf(float x) {
    unsigned u = __float_as_uint(x);
    return (unsigned short)((u + 0x7fffu + ((u >> 16) & 1u)) >> 16);
}
__device__ __forceinline__ float bf2f(unsigned short b) {
    return __uint_as_float((unsigned)b << 16);
}
__device__ __forceinline__ void bfsplit(float x, unsigned short& h, unsigned short& l) {
    h = f2bf(x);
    l = f2bf(x - bf2f(h));
}
__device__ __forceinline__ void mma16(float* d, const unsigned* a, unsigned b0, unsigned b1) {
    asm("mma.sync.aligned.m16n8k16.row.col.f32.bf16.bf16.f32 "
        "{%0,%1,%2,%3},{%4,%5,%6,%7},{%8,%9},{%0,%1,%2,%3};"
        : "+f"(d[0]), "+f"(d[1]), "+f"(d[2]), "+f"(d[3])
        : "r"(a[0]), "r"(a[1]), "r"(a[2]), "r"(a[3]), "r"(b0), "r"(b1));
}
__device__ __forceinline__ void ld64s(const unsigned* p, unsigned& a, unsigned& b) {
    ull v = *(const ull*)p; a = (unsigned)v; b = (unsigned)(v >> 32);
}
// pair-index permutation: adjacent (kq, kq+4) pairs within each kt group of 8
__device__ __forceinline__ int permp(int p) {
    return (p & ~7) + ((p & 3) << 1) + ((p >> 2) & 1);
}

// ---------------- device scratch ----------------
__device__ float    g_logits[NE * NTOK];
__device__ unsigned g_mask[NTOK];
__device__ int      g_cnt[NE];
__device__ int      g_list[NE * NTOK];
__device__ float    g_wl[NE * NTOK];
__device__ unsigned g_te[NTOK];
__device__ float    g_tw0[NTOK];
__device__ float    g_tw1[NTOK];
__device__ __align__(16) unsigned g_w1h[NE*W1PE];
__device__ __align__(16) unsigned g_w1l[NE*W1PE];
__device__ __align__(16) unsigned g_w2h[NE*W2PE];
__device__ __align__(16) unsigned g_w2l[NE*W2PE];
__device__ __align__(16) unsigned g_a1h[NE*A1PE];
__device__ __align__(16) unsigned g_a1l[NE*A1PE];
__device__ __align__(16) unsigned g_a2h[NE*A2PE];
__device__ __align__(16) unsigned g_a2l[NE*A2PE];
// parallel radix select state
__device__ unsigned g_hist[NE][256];
__device__ unsigned g_thr[NE];
__device__ unsigned g_need[NE];
__device__ int      g_ccount[NE][64];
__device__ int      g_cbase[NE][64];

__global__ void init_kernel() {
    int t = blockIdx.x * 1024 + threadIdx.x;
    if (t < NE) { g_cnt[t] = 0; g_thr[t] = 0u; g_need[t] = KCAP; }
    if (t < NE*256) ((unsigned*)g_hist)[t] = 0u;
}

// ---------------- one-shot weight split: fragment-vector bf16 hi/lo planes --
__global__ void __launch_bounds__(1024) split_kernel(
    const float* __restrict__ W1, const float* __restrict__ B1,
    const float* __restrict__ W2, const float* __restrict__ B2,
    const float* __restrict__ A1, const float* __restrict__ A2)
{
    int i = blockIdx.x * 1024 + threadIdx.x;
    if (i < NE*W1PE) {
        int e = i / W1PE, r = i % W1PE;
        int pr = r & 1; int t = r >> 1;
        int nj = t % 6; t /= 6;
        int g  = t % 8; t /= 8;
        int w  = t % 8; t /= 8;
        int kq = t % 4; int kt = t / 4;
        int row = kt*8 + kq + pr*4;
        int k0 = 2*row, k1 = k0 + 1;
        int n = w*48 + nj*8 + g;
        float v0 = (k0 < 192) ? W1[((size_t)e*192 + k0)*384 + n]
                              : B1[((size_t)e*32 + (k0-192))*384 + n];
        float v1 = (k1 < 192) ? W1[((size_t)e*192 + k1)*384 + n]
                              : B1[((size_t)e*32 + (k1-192))*384 + n];
        unsigned short h0,l0,h1,l1;
        bfsplit(v0,h0,l0); bfsplit(v1,h1,l1);
        g_w1h[i] = (unsigned)h0 | ((unsigned)h1 << 16);
        g_w1l[i] = (unsigned)l0 | ((unsigned)l1 << 16);
    }
    if (i < NE*W2PE) {
        int e = i / W2PE, r = i % W2PE;
        int pr = r & 1; int t = r >> 1;
        int nj = t % 4; t /= 4;
        int g  = t % 8; t /= 8;
        int w  = t % 8; t /= 8;
        int kq = t % 4; int kt = t / 4;
        if (nj < 3) {
            int row = kt*8 + kq + pr*4;
            int k0 = 2*row, k1 = k0 + 1;
            int n = w*24 + nj*8 + g;
            float v0 = (k0 < 384) ? W2[((size_t)e*384 + k0)*192 + n]
                                  : B2[((size_t)e*32 + (k0-384))*192 + n];
            float v1 = (k1 < 384) ? W2[((size_t)e*384 + k1)*192 + n]
                                  : B2[((size_t)e*32 + (k1-384))*192 + n];
            unsigned short h0,l0,h1,l1;
            bfsplit(v0,h0,l0); bfsplit(v1,h1,l1);
            g_w2h[i] = (unsigned)h0 | ((unsigned)h1 << 16);
            g_w2l[i] = (unsigned)l0 | ((unsigned)l1 << 16);
        } else {
            g_w2h[i] = 0u; g_w2l[i] = 0u;
        }
    }
    if (i < NE*A1PE) {
        int e = i / A1PE, r = i % A1PE;
        int pr = r & 1; int t = r >> 1;
        int g  = t % 8; t /= 8;
        int nh = t % 4; t /= 4;
        int kq = t % 4; int kt = t / 4;
        int row = kt*8 + kq + pr*4;
        int k0 = 2*row, k1 = k0 + 1;
        const float* A = A1 + ((size_t)(e*4 + nh)*192)*8 + g;
        float v0 = A[(size_t)k0*8], v1 = A[(size_t)k1*8];
        unsigned short h0,l0,h1,l1;
        bfsplit(v0,h0,l0); bfsplit(v1,h1,l1);
        g_a1h[i] = (unsigned)h0 | ((unsigned)h1 << 16);
        g_a1l[i] = (unsigned)l0 | ((unsigned)l1 << 16);
    }
    if (i < NE*A2PE) {
        int e = i / A2PE, r = i % A2PE;
        int pr = r & 1; int t = r >> 1;
        int g  = t % 8; t /= 8;
        int nh = t % 4; t /= 4;
        int kq = t % 4; int kt = t / 4;
        int row = kt*8 + kq + pr*4;
        int k0 = 2*row, k1 = k0 + 1;
        const float* A = A2 + ((size_t)(e*4 + nh)*384)*8 + g;
        float v0 = A[(size_t)k0*8], v1 = A[(size_t)k1*8];
        unsigned short h0,l0,h1,l1;
        bfsplit(v0,h0,l0); bfsplit(v1,h1,l1);
        g_a2h[i] = (unsigned)h0 | ((unsigned)h1 << 16);
        g_a2l[i] = (unsigned)l0 | ((unsigned)l1 << 16);
    }
}

// ---------------- gate: features + LN + logits ----------------
__global__ void __launch_bounds__(1024) gate_kernel(
    const float* __restrict__ x, const float* __restrict__ xprev,
    const float* __restrict__ Wz, const float* __restrict__ lng,
    const float* __restrict__ lnb, const float* __restrict__ Wg,
    const float* __restrict__ bg)
{
    extern __shared__ float sm[];
    float* sWz = sm;              // 12288, pair-interleaved
    float* sWg = sWz + 12288;     // 258*12 stride-12 padded
    float* sg  = sWg + 3096;
    float* sb  = sg + 258;
    float* sbg = sb + 258;
    float* sX  = sbg + 8;         // 32*192

    int tid = threadIdx.x, lane = tid & 31, warp = tid >> 5;
    int n = blockIdx.x * 32 + warp;

    for (int i = tid; i < 12288; i += 1024) {
        int col = i & 63;
        int col2 = ((col & 31) << 1) | (col >> 5);
        sWz[(i & ~63) + col2] = Wz[i];
    }
    for (int i = tid; i < 2064;  i += 1024) sWg[(i >> 3)*12 + (i & 7)] = Wg[i];
    for (int i = tid; i < 258;   i += 1024) { sg[i] = lng[i]; sb[i] = lnb[i]; }
    if (tid < 8) sbg[tid] = bg[tid];

    float xr[6];
    #pragma unroll
    for (int i = 0; i < 6; i++) {
        xr[i] = x[(size_t)n*CIN + lane + 32*i];
        sX[warp*CIN + lane + 32*i] = xr[i];
    }
    float s = 0.f, ss = 0.f;
    #pragma unroll
    for (int i = 0; i < 6; i++) {
        float a = fabsf(xr[i] - xprev[(size_t)n*CIN + lane + 32*i]);
        s += a; ss += a*a;
    }
    #pragma unroll
    for (int o = 16; o; o >>= 1) {
        s  += __shfl_xor_sync(0xffffffffu, s, o);
        ss += __shfl_xor_sync(0xffffffffu, ss, o);
    }
    float dmean = s * (1.0f/192.0f);
    float dvar  = fmaxf((ss - s*dmean) * (1.0f/191.0f), 0.f);
    float mu = log1pf(dmean), sd = log1pf(sqrtf(dvar));

    __syncthreads();

    float z0 = 0.f, z1 = 0.f;
    for (int c = 0; c < CIN; c++) {
        float xv = sX[warp*CIN + c];
        float2 w = *(const float2*)(sWz + c*64 + 2*lane);
        z0 = fmaf(xv, w.x, z0);
        z1 = fmaf(xv, w.y, z1);
    }
    float sa = z0 + z1, s2 = z0*z0 + z1*z1;
    #pragma unroll
    for (int i = 0; i < 6; i++) { sa += xr[i]; s2 += xr[i]*xr[i]; }
    if (lane == 0) { sa += mu + sd; s2 += mu*mu + sd*sd; }
    #pragma unroll
    for (int o = 16; o; o >>= 1) {
        sa += __shfl_xor_sync(0xffffffffu, sa, o);
        s2 += __shfl_xor_sync(0xffffffffu, s2, o);
    }
    float m_   = sa * (1.0f/258.0f);
    float rstd = rsqrtf(s2 * (1.0f/258.0f) - m_*m_ + 1e-5f);

    float acc[8] = {0,0,0,0,0,0,0,0};
    #pragma unroll
    for (int i = 0; i < 6; i++) {
        int idx = lane + 32*i;
        float nv = (xr[i] - m_)*rstd*sg[idx] + sb[idx];
        float4 wa = *(const float4*)(sWg + idx*12);
        float4 wb = *(const float4*)(sWg + idx*12 + 4);
        acc[0]=fmaf(nv,wa.x,acc[0]); acc[1]=fmaf(nv,wa.y,acc[1]);
        acc[2]=fmaf(nv,wa.z,acc[2]); acc[3]=fmaf(nv,wa.w,acc[3]);
        acc[4]=fmaf(nv,wb.x,acc[4]); acc[5]=fmaf(nv,wb.y,acc[5]);
        acc[6]=fmaf(nv,wb.z,acc[6]); acc[7]=fmaf(nv,wb.w,acc[7]);
    }
    {
        int idx = 192 + lane;
        float nv = (z0 - m_)*rstd*sg[idx] + sb[idx];
        float4 wa = *(const float4*)(sWg + idx*12);
        float4 wb = *(const float4*)(sWg + idx*12 + 4);
        acc[0]=fmaf(nv,wa.x,acc[0]); acc[1]=fmaf(nv,wa.y,acc[1]);
        acc[2]=fmaf(nv,wa.z,acc[2]); acc[3]=fmaf(nv,wa.w,acc[3]);
        acc[4]=fmaf(nv,wb.x,acc[4]); acc[5]=fmaf(nv,wb.y,acc[5]);
        acc[6]=fmaf(nv,wb.z,acc[6]); acc[7]=fmaf(nv,wb.w,acc[7]);
        idx = 224 + lane;
        nv = (z1 - m_)*rstd*sg[idx] + sb[idx];
        wa = *(const float4*)(sWg + idx*12);
        wb = *(const float4*)(sWg + idx*12 + 4);
        acc[0]=fmaf(nv,wa.x,acc[0]); acc[1]=fmaf(nv,wa.y,acc[1]);
        acc[2]=fmaf(nv,wa.z,acc[2]); acc[3]=fmaf(nv,wa.w,acc[3]);
        acc[4]=fmaf(nv,wb.x,acc[4]); acc[5]=fmaf(nv,wb.y,acc[5]);
        acc[6]=fmaf(nv,wb.z,acc[6]); acc[7]=fmaf(nv,wb.w,acc[7]);
    }
    if (lane == 0) {
        float nv = (mu - m_)*rstd*sg[256] + sb[256];
        float4 wa = *(const float4*)(sWg + 256*12);
        float4 wb = *(const float4*)(sWg + 256*12 + 4);
        acc[0]=fmaf(nv,wa.x,acc[0]); acc[1]=fmaf(nv,wa.y,acc[1]);
        acc[2]=fmaf(nv,wa.z,acc[2]); acc[3]=fmaf(nv,wa.w,acc[3]);
        acc[4]=fmaf(nv,wb.x,acc[4]); acc[5]=fmaf(nv,wb.y,acc[5]);
        acc[6]=fmaf(nv,wb.z,acc[6]); acc[7]=fmaf(nv,wb.w,acc[7]);
        nv = (sd - m_)*rstd*sg[257] + sb[257];
        wa = *(const float4*)(sWg + 257*12);
        wb = *(const float4*)(sWg + 257*12 + 4);
        acc[0]=fmaf(nv,wa.x,acc[0]); acc[1]=fmaf(nv,wa.y,acc[1]);
        acc[2]=fmaf(nv,wa.z,acc[2]); acc[3]=fmaf(nv,wa.w,acc[3]);
        acc[4]=fmaf(nv,wb.x,acc[4]); acc[5]=fmaf(nv,wb.y,acc[5]);
        acc[6]=fmaf(nv,wb.z,acc[6]); acc[7]=fmaf(nv,wb.w,acc[7]);
    }
    #pragma unroll
    for (int e = 0; e < 8; e++) {
        #pragma unroll
        for (int o = 16; o; o >>= 1) acc[e] += __shfl_xor_sync(0xffffffffu, acc[e], o);
    }
    if (lane == 0) {
        #pragma unroll
        for (int e = 0; e < 8; e++) g_logits[e*NTOK + n] = acc[e] + sbg[e];
        g_mask[n] = 0u;
    }
}

// ---------------- parallel radix select ----------------
__device__ __forceinline__ unsigned f2key(float f) {
    unsigned u = __float_as_uint(f);
    return (u & 0x80000000u) ? ~u : (u | 0x80000000u);
}

__global__ void __launch_bounds__(256) hist_kernel(int shift) {
    __shared__ unsigned hist[256];
    int e = blockIdx.y, tid = threadIdx.x, lane = tid & 31;
    hist[tid] = 0;
    __syncthreads();
    unsigned pmask = (shift == 24) ? 0u : (0xFFFFFFFFu << (shift + 8));
    unsigned prefix = g_thr[e] & pmask;
    const float* base = g_logits + (size_t)e * NTOK;
    int n0 = blockIdx.x * 2048;
    for (int i = tid; i < 2048; i += 256) {
        unsigned k = f2key(base[n0 + i]);
        bool act = ((k & pmask) == prefix);
        unsigned dg = act ? ((k >> shift) & 255u) : 0xffffffffu;
        unsigned peers = __match_any_sync(0xffffffffu, dg);
        if (act && (__ffs(peers) - 1) == lane)
            atomicAdd(&hist[dg], (unsigned)__popc(peers));
    }
    __syncthreads();
    if (hist[tid]) atomicAdd(&g_hist[e][tid], hist[tid]);
}

__global__ void __launch_bounds__(32) digit_kernel(int shift) {
    int e = blockIdx.x, lane = threadIdx.x;
    unsigned need = g_need[e];
    unsigned v[8];
    unsigned lsum = 0;
    #pragma unroll
    for (int j = 0; j < 8; j++) {
        v[j] = g_hist[e][255 - (lane*8 + j)];
        lsum += v[j];
    }
    unsigned inc = lsum;
    #pragma unroll
    for (int o = 1; o < 32; o <<= 1) {
        unsigned t = __shfl_up_sync(0xffffffffu, inc, o);
        if (lane >= o) inc += t;
    }
    unsigned pre = inc - lsum;
    bool crossing = (pre < need) && (pre + lsum >= need);
    if (crossing) {
        unsigned cum = pre;
        #pragma unroll
        for (int j = 0; j < 8; j++) {
            int d = 255 - (lane*8 + j);
            if (d == 0 || cum + v[j] >= need) {
                g_thr[e] |= ((unsigned)d) << shift;
                g_need[e] = need - cum;
                break;
            }
            cum += v[j];
        }
    }
    __syncwarp();
    #pragma unroll
    for (int j = 0; j < 8; j++) g_hist[e][lane*8 + j] = 0u;
}

__global__ void __launch_bounds__(256) mark_kernel() {
    int e = blockIdx.y, c = blockIdx.x, tid = threadIdx.x, lane = tid & 31;
    unsigned thr = g_thr[e];
    const float* base = g_logits + (size_t)e * NTOK;
    int cnt = 0;
    for (int i = tid; i < 1024; i += 256) {
        unsigned k = f2key(base[c*1024 + i]);
        if (k > thr) atomicOr(&g_mask[c*1024 + i], 1u << e);
        cnt += (k == thr);
    }
    #pragma unroll
    for (int o = 16; o; o >>= 1) cnt += __shfl_xor_sync(0xffffffffu, cnt, o);
    __shared__ int ws[8];
    if (lane == 0) ws[tid >> 5] = cnt;
    __syncthreads();
    if (tid == 0) {
        int t = 0;
        for (int w = 0; w < 8; w++) t += ws[w];
        g_ccount[e][c] = t;
    }
}

__global__ void __launch_bounds__(32) scan_kernel() {
    int e = blockIdx.x;
    if (threadIdx.x == 0) {
        int run = 0;
        for (int c = 0; c < 64; c++) { g_cbase[e][c] = run; run += g_ccount[e][c]; }
    }
}

__global__ void __launch_bounds__(32) tie_kernel() {
    int e = blockIdx.y, c = blockIdx.x, lane = threadIdx.x;
    int r = (int)g_need[e];
    int rank = g_cbase[e][c];
    if (rank >= r) return;
    unsigned thr = g_thr[e];
    const float* base = g_logits + (size_t)e * NTOK;
    for (int s = 0; s < 32; s++) {
        int n = c*1024 + s*32 + lane;
        bool p = (f2key(base[n]) == thr);
        unsigned bal = __ballot_sync(0xffffffffu, p);
        int myrank = rank + __popc(bal & ((1u << lane) - 1u));
        if (p && myrank < r) atomicOr(&g_mask[n], 1u << e);
        rank += __popc(bal);
        if (rank >= r) break;
    }
}

// ---------------- routing (block-aggregated dispatch) ----------------
__global__ void __launch_bounds__(256) route_kernel(float* __restrict__ out) {
    __shared__ int sCnt[8], sBase[8];
    int tid = threadIdx.x;
    int n = blockIdx.x * 256 + tid;
    if (tid < 8) sCnt[tid] = 0;
    __syncthreads();

    float l[8];
    #pragma unroll
    for (int e = 0; e < 8; e++) l[e] = g_logits[e*NTOK + n];
    unsigned m = g_mask[n];
    if (m == 0u) {
        int best = 0; float bv = l[0];
        #pragma unroll
        for (int e = 1; e < 8; e++) if (l[e] > bv) { bv = l[e]; best = e; }
        m = 1u << best;
    }
    int e0 = -1, e1 = -1; float v0 = -INFINITY, v1 = -INFINITY;
    #pragma unroll
    for (int e = 0; e < 8; e++) {
        if ((m >> e) & 1u) {
            float f = l[e];
            if (f > v0)      { v1 = v0; e1 = e0; v0 = f; e0 = e; }
            else if (f > v1) { v1 = f; e1 = e; }
        }
    }
    float w0 = 1.f, w1 = 0.f;
    if (e1 >= 0) {
        float ex = expf(v1 - v0);
        w0 = 1.0f / (1.0f + ex);
        w1 = ex * w0;
    }
    bool has1 = (e1 >= 0 && w1 > 0.f);
    int p0 = atomicAdd(&sCnt[e0], 1);
    int p1 = has1 ? atomicAdd(&sCnt[e1], 1) : -1;
    __syncthreads();
    if (tid < 8) sBase[tid] = atomicAdd(&g_cnt[tid], sCnt[tid]);
    __syncthreads();
    {
        int pos = sBase[e0] + p0;
        g_list[e0*NTOK + pos] = n;
        g_wl[e0*NTOK + pos]   = w0;
    }
    unsigned te = (unsigned)e0 | (255u << 8);
    float tw1 = 0.f;
    if (has1) {
        int pos = sBase[e1] + p1;
        g_list[e1*NTOK + pos] = n;
        g_wl[e1*NTOK + pos]   = w1;
        te = (unsigned)e0 | ((unsigned)e1 << 8);
        tw1 = w1;
    }
    g_te[n] = te; g_tw0[n] = w0; g_tw1[n] = tw1;

    float4 z4 = make_float4(0.f, 0.f, 0.f, 0.f);
    float4* o4 = (float4*)out;
    for (int i = n; i < NTOK*OUTD/4; i += NTOK) o4[i] = z4;
}

// ---------------- fused expert FFN v16: vectorized fragments ----------------
__global__ void __launch_bounds__(256, 2) ffn_kernel(
    const float* __restrict__ x,  const float* __restrict__ bw,
    const float* __restrict__ b1, const float* __restrict__ b2,
    float* __restrict__ out)
{
    extern __shared__ float sm[];
    unsigned* um = (unsigned*)sm;
    float* sBw = sm + OFF_BW;
    float* sGw = sm + OFF_GW;
    int*   sTok = (int*)(sm + OFF_TOK);

    int e = blockIdx.y;
    int cnt = g_cnt[e];
    int t0 = blockIdx.x * TTILE;
    if (t0 >= cnt) return;
    int nt = min(TTILE, cnt - t0);
    int tid = threadIdx.x;

    if (tid < TTILE) {
        int idx = t0 + min(tid, nt - 1);
        int tok = g_list[e*NTOK + idx];
        sTok[tid] = tok;
        sGw[tid]  = (tid < nt) ? g_wl[e*NTOK + idx] : 0.f;
        *(float4*)(sBw + tid*4) = *(const float4*)(bw + (size_t)tok*4);
    }
    __syncthreads();

    {   // gather x -> pair-interleaved packed bf16 hi/lo planes [tok][perm(p)]
        int t = tid & 31, part = tid >> 3 & 0; // placeholder removed below
        part = tid >> 5;
        int tok = sTok[t];
        const float4* src = (const float4*)(x + (size_t)tok*CIN) + part*6;
        #pragma unroll
        for (int i = 0; i < 6; i++) {
            float4 v = src[i];
            unsigned short h0,l0,h1,l1,h2,l2,h3,l3;
            bfsplit(v.x,h0,l0); bfsplit(v.y,h1,l1);
            bfsplit(v.z,h2,l2); bfsplit(v.w,h3,l3);
            int p0 = part*12 + 2*i;
            int o0 = permp(p0), o1 = permp(p0 + 1);
            um[t*XW32 + o0]          = (unsigned)h0 | ((unsigned)h1 << 16);
            um[t*XW32 + o1]          = (unsigned)h2 | ((unsigned)h3 << 16);
            um[OFF_XL + t*XW32 + o0] = (unsigned)l0 | ((unsigned)l1 << 16);
            um[OFF_XL + t*XW32 + o1] = (unsigned)l2 | ((unsigned)l3 << 16);
        }
    }
    __syncthreads();

    int warp = tid >> 5, lane = tid & 31;
    int g = lane >> 2, kq = lane & 3;

    // LoRA1 as MMA: [32,192]x[192,32]
    {
        int mt = warp >> 2, nh = warp & 3;
        float d[4] = {0,0,0,0};
        const unsigned* a1h = g_a1h + (size_t)e*A1PE;
        const unsigned* a1l = g_a1l + (size_t)e*A1PE;
        int rowA = mt*16 + g;
        #pragma unroll
        for (int kt = 0; kt < 12; kt++) {
            unsigned ah[4], al[4];
            int b0 = rowA*XW32 + kt*8 + 2*kq;
            ld64s(um + b0,            ah[0], ah[2]);
            ld64s(um + b0 + 8*XW32,   ah[1], ah[3]);
            ld64s(um + OFF_XL + b0,          al[0], al[2]);
            ld64s(um + OFF_XL + b0 + 8*XW32, al[1], al[3]);
            int wi = (((kt*4 + kq)*4 + nh)*8 + g)*2;
            uint2 bh = *(const uint2*)(a1h + wi);
            uint2 bl = *(const uint2*)(a1l + wi);
            mma16(d, ah, bh.x, bh.y);
            mma16(d, ah, bl.x, bl.y);
            mma16(d, al, bh.x, bh.y);
        }
        int off = (12 + (nh >> 1))*8 + 2*kq + (nh & 1);
        #pragma unroll
        for (int half = 0; half < 2; half++) {
            int t = mt*16 + g + half*8;
            float scl = LSCALE * sBw[t*4 + nh];
            unsigned short h0,l0,h1,l1;
            bfsplit(scl*d[2*half],   h0, l0);
            bfsplit(scl*d[2*half+1], h1, l1);
            um[t*XW32 + off]          = (unsigned)h0 | ((unsigned)h1 << 16);
            um[OFF_XL + t*XW32 + off] = (unsigned)l0 | ((unsigned)l1 << 16);
        }
    }
    __syncthreads();

    // ---- layer 1: [32,224]x[224,384]; warp = 2 M-tiles x 48 cols ----
    float d1[2][6][4];
    #pragma unroll
    for (int nj = 0; nj < 6; nj++) {
        int col = warp*48 + nj*8 + 2*kq;
        float b0v = b1[e*HID + col], b1v = b1[e*HID + col + 1];
        #pragma unroll
        for (int mt = 0; mt < 2; mt++) {
            d1[mt][nj][0] = b0v; d1[mt][nj][1] = b1v;
            d1[mt][nj][2] = b0v; d1[mt][nj][3] = b1v;
        }
    }
    const unsigned* w1h = g_w1h + (size_t)e*W1PE;
    const unsigned* w1l = g_w1l + (size_t)e*W1PE;
    for (int kt = 0; kt < 14; kt++) {
        unsigned ah[2][4], al[2][4];
        #pragma unroll
        for (int mt = 0; mt < 2; mt++) {
            int b0 = (mt*16 + g)*XW32 + kt*8 + 2*kq;
            ld64s(um + b0,            ah[mt][0], ah[mt][2]);
            ld64s(um + b0 + 8*XW32,   ah[mt][1], ah[mt][3]);
            ld64s(um + OFF_XL + b0,          al[mt][0], al[mt][2]);
            ld64s(um + OFF_XL + b0 + 8*XW32, al[mt][1], al[mt][3]);
        }
        const unsigned* Wh = w1h + ((kt*4 + kq)*8 + warp)*96 + g*12;
        const unsigned* Wl = w1l + ((kt*4 + kq)*8 + warp)*96 + g*12;
        #pragma unroll
        for (int jj = 0; jj < 3; jj++) {
            uint4 H = *(const uint4*)(Wh + jj*4);
            uint4 L = *(const uint4*)(Wl + jj*4);
            #pragma unroll
            for (int mt = 0; mt < 2; mt++) {
                mma16(d1[mt][2*jj],   ah[mt], H.x, H.y);
                mma16(d1[mt][2*jj],   ah[mt], L.x, L.y);
                mma16(d1[mt][2*jj],   al[mt], H.x, H.y);
                mma16(d1[mt][2*jj+1], ah[mt], H.z, H.w);
                mma16(d1[mt][2*jj+1], ah[mt], L.z, L.w);
                mma16(d1[mt][2*jj+1], al[mt], H.z, H.w);
            }
        }
    }
    __syncthreads();   // X reads done; H overwrites the union region

    // exact GELU -> pair-interleaved packed bf16 split H
    #pragma unroll
    for (int mt = 0; mt < 2; mt++)
        #pragma unroll
        for (int nj = 0; nj < 6; nj++) {
            int off = (3*warp + (nj >> 1))*8 + 2*kq + (nj & 1);
            #pragma unroll
            for (int half = 0; half < 2; half++) {
                int t = mt*16 + g + half*8;
                float v0 = d1[mt][nj][2*half], v1 = d1[mt][nj][2*half + 1];
                float g0 = v0 * 0.5f * (1.0f + erff(v0 * 0.70710678118654752f));
                float g1 = v1 * 0.5f * (1.0f + erff(v1 * 0.70710678118654752f));
                unsigned short h0,l0,h1,l1;
                bfsplit(g0,h0,l0); bfsplit(g1,h1,l1);
                um[t*HW32 + off]          = (unsigned)h0 | ((unsigned)h1 << 16);
                um[OFF_HL + t*HW32 + off] = (unsigned)l0 | ((unsigned)l1 << 16);
            }
        }
    __syncthreads();

    // LoRA2 as MMA: [32,384]x[384,32]
    {
        int mt = warp >> 2, nh = warp & 3;
        float d[4] = {0,0,0,0};
        const unsigned* a2h = g_a2h + (size_t)e*A2PE;
        const unsigned* a2l = g_a2l + (size_t)e*A2PE;
        int rowA = mt*16 + g;
        #pragma unroll 4
        for (int kt = 0; kt < 24; kt++) {
            unsigned ah[4], al[4];
            int b0 = rowA*HW32 + kt*8 + 2*kq;
            ld64s(um + b0,            ah[0], ah[2]);
            ld64s(um + b0 + 8*HW32,   ah[1], ah[3]);
            ld64s(um + OFF_HL + b0,          al[0], al[2]);
            ld64s(um + OFF_HL + b0 + 8*HW32, al[1], al[3]);
            int wi = (((kt*4 + kq)*4 + nh)*8 + g)*2;
            uint2 bh = *(const uint2*)(a2h + wi);
            uint2 bl = *(const uint2*)(a2l + wi);
            mma16(d, ah, bh.x, bh.y);
            mma16(d, ah, bl.x, bl.y);
            mma16(d, al, bh.x, bh.y);
        }
        int off = (24 + (nh >> 1))*8 + 2*kq + (nh & 1);
        #pragma unroll
        for (int half = 0; half < 2; half++) {
            int t = mt*16 + g + half*8;
            float scl = LSCALE * sBw[t*4 + nh];
            unsigned short h0,l0,h1,l1;
            bfsplit(scl*d[2*half],   h0, l0);
            bfsplit(scl*d[2*half+1], h1, l1);
            um[t*HW32 + off]          = (unsigned)h0 | ((unsigned)h1 << 16);
            um[OFF_HL + t*HW32 + off] = (unsigned)l0 | ((unsigned)l1 << 16);
        }
    }
    __syncthreads();

    // ---- layer 2: [32,416]x[416,192]; warp = 2 M-tiles x 24 cols ----
    float d2[2][3][4];
    #pragma unroll
    for (int nj = 0; nj < 3; nj++) {
        int col = warp*24 + nj*8 + 2*kq;
        float b0v = b2[e*OUTD + col], b1v = b2[e*OUTD + col + 1];
        #pragma unroll
        for (int mt = 0; mt < 2; mt++) {
            d2[mt][nj][0] = b0v; d2[mt][nj][1] = b1v;
            d2[mt][nj][2] = b0v; d2[mt][nj][3] = b1v;
        }
    }
    const unsigned* w2h = g_w2h + (size_t)e*W2PE;
    const unsigned* w2l = g_w2l + (size_t)e*W2PE;
    for (int kt = 0; kt < 26; kt++) {
        unsigned ah[2][4], al[2][4];
        #pragma unroll
        for (int mt = 0; mt < 2; mt++) {
            int b0 = (mt*16 + g)*HW32 + kt*8 + 2*kq;
            ld64s(um + b0,            ah[mt][0], ah[mt][2]);
            ld64s(um + b0 + 8*HW32,   ah[mt][1], ah[mt][3]);
            ld64s(um + OFF_HL + b0,          al[mt][0], al[mt][2]);
            ld64s(um + OFF_HL + b0 + 8*HW32, al[mt][1], al[mt][3]);
        }
        const unsigned* Wh = w2h + ((kt*4 + kq)*8 + warp)*64 + g*8;
        const unsigned* Wl = w2l + ((kt*4 + kq)*8 + warp)*64 + g*8;
        uint4 H = *(const uint4*)(Wh);
        uint2 Hy = *(const uint2*)(Wh + 4);
        uint4 L = *(const uint4*)(Wl);
        uint2 Ly = *(const uint2*)(Wl + 4);
        #pragma unroll
        for (int mt = 0; mt < 2; mt++) {
            mma16(d2[mt][0], ah[mt], H.x, H.y);
            mma16(d2[mt][0], ah[mt], L.x, L.y);
            mma16(d2[mt][0], al[mt], H.x, H.y);
            mma16(d2[mt][1], ah[mt], H.z, H.w);
            mma16(d2[mt][1], ah[mt], L.z, L.w);
            mma16(d2[mt][1], al[mt], H.z, H.w);
            mma16(d2[mt][2], ah[mt], Hy.x, Hy.y);
            mma16(d2[mt][2], ah[mt], Ly.x, Ly.y);
            mma16(d2[mt][2], al[mt], Hy.x, Hy.y);
        }
    }
    // epilogue
    #pragma unroll
    for (int mt = 0; mt < 2; mt++)
        #pragma unroll
        for (int nj = 0; nj < 3; nj++) {
            int col = warp*24 + nj*8 + 2*kq;
            #pragma unroll
            for (int q = 0; q < 4; q++) {
                int t = mt*16 + g + (q >> 1)*8;
                if (t < nt) {
                    int tok = sTok[t];
                    atomicAdd(&out[(size_t)tok*OUTD + col + (q & 1)],
                              sGw[t]*d2[mt][nj][q]);
                }
            }
        }
}

// ---------------- deterministic loss ----------------
__global__ void __launch_bounds__(1024) loss_kernel(float* out, int out_size) {
    __shared__ float sI[8][32], sL[8][32];
    int tid = threadIdx.x, lane = tid & 31, warp = tid >> 5;
    float imp[8] = {0,0,0,0,0,0,0,0}, ld[8] = {0,0,0,0,0,0,0,0};
    for (int n = tid; n < NTOK; n += 1024) {
        unsigned te = g_te[n];
        int e0 = te & 255u, e1 = (te >> 8) & 255u;
        imp[e0] += g_tw0[n]; ld[e0] += 1.f;
        if (e1 != 255) { imp[e1] += g_tw1[n]; ld[e1] += 1.f; }
    }
    #pragma unroll
    for (int e = 0; e < 8; e++) {
        #pragma unroll
        for (int o = 16; o; o >>= 1) {
            imp[e] += __shfl_xor_sync(0xffffffffu, imp[e], o);
            ld[e]  += __shfl_xor_sync(0xffffffffu, ld[e],  o);
        }
        if (lane == 0) { sI[e][warp] = imp[e]; sL[e][warp] = ld[e]; }
    }
    __syncthreads();
    if (tid == 0) {
        float I[8], L[8], mi = 0.f, ml = 0.f;
        for (int e = 0; e < 8; e++) {
            float a = 0.f, b = 0.f;
            for (int w = 0; w < 32; w++) { a += sI[e][w]; b += sL[e][w]; }
            I[e] = a; L[e] = b; mi += a; ml += b;
        }
        mi *= 0.125f; ml *= 0.125f;
        float vi = 0.f, vl = 0.f;
        for (int e = 0; e < 8; e++) {
            float di = I[e] - mi; vi += di*di;
            float dl = L[e] - ml; vl += dl*dl;
        }
        vi *= 0.125f; vl *= 0.125f;
        float loss = (vi / (mi*mi + 1e-10f) + vl / (ml*ml + 1e-10f)) * 0.01f;
        if (out_size > NTOK*OUTD) out[NTOK*OUTD] = loss;
    }
    for (int i = NTOK*OUTD + 1 + tid; i < out_size; i += 1024) out[i] = 0.f;
}

// ---------------- launch ----------------
extern "C" void kernel_launch(void* const* d_in, const int* in_sizes, int n_in,
                              void* d_out, int out_size) {
    const float* x     = (const float*)d_in[0];
    const float* bw    = (const float*)d_in[1];
    const float* xprev = (const float*)d_in[2];
    const float* Wz    = (const float*)d_in[3];
    const float* lng   = (const float*)d_in[4];
    const float* lnb   = (const float*)d_in[5];
    const float* Wg    = (const float*)d_in[6];
    const float* bg    = (const float*)d_in[7];
    const float* W1    = (const float*)d_in[8];
    const float* b1    = (const float*)d_in[9];
    const float* W2    = (const float*)d_in[10];
    const float* b2    = (const float*)d_in[11];
    const float* A1    = (const float*)d_in[12];
    const float* B1    = (const float*)d_in[13];
    const float* A2    = (const float*)d_in[14];
    const float* B2    = (const float*)d_in[15];
    float* out = (float*)d_out;

    const size_t GATE_SMEM = (size_t)(12288 + 3096 + 258 + 258 + 8 + 32*192) * 4;
    const size_t FFN_SMEM  = (size_t)FFN_U32 * 4;
    cudaFuncSetAttribute(gate_kernel, cudaFuncAttributeMaxDynamicSharedMemorySize, (int)GATE_SMEM);
    cudaFuncSetAttribute(ffn_kernel,  cudaFuncAttributeMaxDynamicSharedMemorySize, (int)FFN_SMEM);

    init_kernel<<<2, 1024>>>();
    split_kernel<<<(NE*W2PE + 1023)/1024, 1024>>>(W1, B1, W2, B2, A1, A2);
    gate_kernel<<<NTOK/32, 1024, GATE_SMEM>>>(x, xprev, Wz, lng, lnb, Wg, bg);
    for (int p = 0; p < 4; p++) {
        int shift = 24 - p*8;
        hist_kernel<<<dim3(32, NE), 256>>>(shift);
        digit_kernel<<<NE, 32>>>(shift);
    }
    mark_kernel<<<dim3(64, NE), 256>>>();
    scan_kernel<<<NE, 32>>>();
    tie_kernel<<<dim3(64, NE), 32>>>();
    route_kernel<<<NTOK/256, 256>>>(out);
    ffn_kernel<<<dim3(NTOK/TTILE, NE), 256, FFN_SMEM>>>(x, bw, b1, b2, out);
    loss_kernel<<<1, 1024>>>(out, out_size);
}

// round 17
// speedup vs baseline: 1.5565x; 1.5565x over previous
#include <cuda_runtime.h>
#include <math.h>
#include <stdint.h>

#define NTOK 65536
#define CIN 192
#define HID 384
#define OUTD 192
#define NE 8
#define KCAP 10240
#define TTILE 32
#define LSCALE 2.0f

// FFN smem (u32 units); X/H planes share a union; pair-interleaved rows
#define XW32   116
#define HW32   212
#define OFF_XL 3712      /* 32*116 */
#define OFF_HL 6784      /* 32*212 */
#define OFF_BW 13568
#define OFF_GW 13696
#define OFF_TOK 13728
#define FFN_U32 13760

// pair-interleaved, n-major coalesced weight planes (u32 per expert)
#define W1PE 43008       /* 14kt*4kq*384n*2s */
#define W2PE 39936       /* 26kt*4kq*192n*2s */
#define A1PE 3072        /* 12kt*4kq*32col*2s */
#define A2PE 6144        /* 24kt*4kq*32col*2s */

typedef unsigned long long ull;

__device__ __forceinline__ unsigned short f2bf(float x) {
    unsigned u = __float_as_uint(x);
    return (unsigned short)((u + 0x7fffu + ((u >> 16) & 1u)) >> 16);
}
__device__ __forceinline__ float bf2f(unsigned short b) {
    return __uint_as_float((unsigned)b << 16);
}
__device__ __forceinline__ void bfsplit(float x, unsigned short& h, unsigned short& l) {
    h = f2bf(x);
    l = f2bf(x - bf2f(h));
}
__device__ __forceinline__ void mma16(float* d, const unsigned* a, unsigned b0, unsigned b1) {
    asm("mma.sync.aligned.m16n8k16.row.col.f32.bf16.bf16.f32 "
        "{%0,%1,%2,%3},{%4,%5,%6,%7},{%8,%9},{%0,%1,%2,%3};"
        : "+f"(d[0]), "+f"(d[1]), "+f"(d[2]), "+f"(d[3])
        : "r"(a[0]), "r"(a[1]), "r"(a[2]), "r"(a[3]), "r"(b0), "r"(b1));
}
__device__ __forceinline__ void ld64s(const unsigned* p, unsigned& a, unsigned& b) {
    ull v = *(const ull*)p; a = (unsigned)v; b = (unsigned)(v >> 32);
}
// pair-index permutation: (kq, kq+4) pairs adjacent within each group of 8
__device__ __forceinline__ int permp(int p) {
    return (p & ~7) + ((p & 3) << 1) + ((p >> 2) & 1);
}

// ---------------- device scratch ----------------
__device__ float    g_logits[NE * NTOK];
__device__ unsigned g_mask[NTOK];
__device__ int      g_cnt[NE];
__device__ int      g_list[NE * NTOK];
__device__ float    g_wl[NE * NTOK];
__device__ unsigned g_te[NTOK];
__device__ float    g_tw0[NTOK];
__device__ float    g_tw1[NTOK];
__device__ __align__(16) unsigned g_w1h[NE*W1PE];
__device__ __align__(16) unsigned g_w1l[NE*W1PE];
__device__ __align__(16) unsigned g_w2h[NE*W2PE];
__device__ __align__(16) unsigned g_w2l[NE*W2PE];
__device__ __align__(16) unsigned g_a1h[NE*A1PE];
__device__ __align__(16) unsigned g_a1l[NE*A1PE];
__device__ __align__(16) unsigned g_a2h[NE*A2PE];
__device__ __align__(16) unsigned g_a2l[NE*A2PE];
// parallel radix select state
__device__ unsigned g_hist[NE][256];
__device__ unsigned g_thr[NE];
__device__ unsigned g_need[NE];
__device__ int      g_ccount[NE][64];
__device__ int      g_cbase[NE][64];

__global__ void init_kernel() {
    int t = blockIdx.x * 1024 + threadIdx.x;
    if (t < NE) { g_cnt[t] = 0; g_thr[t] = 0u; g_need[t] = KCAP; }
    if (t < NE*256) ((unsigned*)g_hist)[t] = 0u;
}

// ---------------- one-shot weight split: coalesced pair-interleaved planes --
__global__ void __launch_bounds__(1024) split_kernel(
    const float* __restrict__ W1, const float* __restrict__ B1,
    const float* __restrict__ W2, const float* __restrict__ B2,
    const float* __restrict__ A1, const float* __restrict__ A2)
{
    int i = blockIdx.x * 1024 + threadIdx.x;
    if (i < NE*112*384) {
        int e = i / 43008, rem = i % 43008;
        int kp = rem / 384, n = rem % 384;
        int kt = kp >> 3, r8 = kp & 7, kq = r8 & 3, s = r8 >> 2;
        int k0 = 2*kp, k1 = k0 + 1;
        float v0 = (k0 < 192) ? W1[((size_t)e*192 + k0)*384 + n]
                              : B1[((size_t)e*32 + (k0-192))*384 + n];
        float v1 = (k1 < 192) ? W1[((size_t)e*192 + k1)*384 + n]
                              : B1[((size_t)e*32 + (k1-192))*384 + n];
        unsigned short h0,l0,h1,l1;
        bfsplit(v0,h0,l0); bfsplit(v1,h1,l1);
        size_t dst = (size_t)e*W1PE + ((size_t)((kt*4 + kq)*384 + n))*2 + s;
        g_w1h[dst] = (unsigned)h0 | ((unsigned)h1 << 16);
        g_w1l[dst] = (unsigned)l0 | ((unsigned)l1 << 16);
    }
    if (i < NE*208*192) {
        int e = i / 39936, rem = i % 39936;
        int kp = rem / 192, n = rem % 192;
        int kt = kp >> 3, r8 = kp & 7, kq = r8 & 3, s = r8 >> 2;
        int k0 = 2*kp, k1 = k0 + 1;
        float v0 = (k0 < 384) ? W2[((size_t)e*384 + k0)*192 + n]
                              : B2[((size_t)e*32 + (k0-384))*192 + n];
        float v1 = (k1 < 384) ? W2[((size_t)e*384 + k1)*192 + n]
                              : B2[((size_t)e*32 + (k1-384))*192 + n];
        unsigned short h0,l0,h1,l1;
        bfsplit(v0,h0,l0); bfsplit(v1,h1,l1);
        size_t dst = (size_t)e*W2PE + ((size_t)((kt*4 + kq)*192 + n))*2 + s;
        g_w2h[dst] = (unsigned)h0 | ((unsigned)h1 << 16);
        g_w2l[dst] = (unsigned)l0 | ((unsigned)l1 << 16);
    }
    if (i < NE*96*32) {
        int e = i / 3072, rem = i % 3072;
        int kp = rem / 32, col = rem & 31;
        int kt = kp >> 3, r8 = kp & 7, kq = r8 & 3, s = r8 >> 2;
        int b = col >> 3, r = col & 7;
        int k0 = 2*kp, k1 = k0 + 1;
        const float* A = A1 + ((size_t)(e*4 + b)*192)*8 + r;
        float v0 = A[(size_t)k0*8], v1 = A[(size_t)k1*8];
        unsigned short h0,l0,h1,l1;
        bfsplit(v0,h0,l0); bfsplit(v1,h1,l1);
        size_t dst = (size_t)e*A1PE + ((size_t)((kt*4 + kq)*32 + col))*2 + s;
        g_a1h[dst] = (unsigned)h0 | ((unsigned)h1 << 16);
        g_a1l[dst] = (unsigned)l0 | ((unsigned)l1 << 16);
    }
    if (i < NE*192*32) {
        int e = i / 6144, rem = i % 6144;
        int kp = rem / 32, col = rem & 31;
        int kt = kp >> 3, r8 = kp & 7, kq = r8 & 3, s = r8 >> 2;
        int b = col >> 3, r = col & 7;
        int k0 = 2*kp, k1 = k0 + 1;
        const float* A = A2 + ((size_t)(e*4 + b)*384)*8 + r;
        float v0 = A[(size_t)k0*8], v1 = A[(size_t)k1*8];
        unsigned short h0,l0,h1,l1;
        bfsplit(v0,h0,l0); bfsplit(v1,h1,l1);
        size_t dst = (size_t)e*A2PE + ((size_t)((kt*4 + kq)*32 + col))*2 + s;
        g_a2h[dst] = (unsigned)h0 | ((unsigned)h1 << 16);
        g_a2l[dst] = (unsigned)l0 | ((unsigned)l1 << 16);
    }
}

// ---------------- gate: features + LN + logits ----------------
__global__ void __launch_bounds__(1024) gate_kernel(
    const float* __restrict__ x, const float* __restrict__ xprev,
    const float* __restrict__ Wz, const float* __restrict__ lng,
    const float* __restrict__ lnb, const float* __restrict__ Wg,
    const float* __restrict__ bg)
{
    extern __shared__ float sm[];
    float* sWz = sm;              // 12288, pair-interleaved
    float* sWg = sWz + 12288;     // 258*12 stride-12 padded
    float* sg  = sWg + 3096;
    float* sb  = sg + 258;
    float* sbg = sb + 258;
    float* sX  = sbg + 8;         // 32*192

    int tid = threadIdx.x, lane = tid & 31, warp = tid >> 5;
    int n = blockIdx.x * 32 + warp;

    for (int i = tid; i < 12288; i += 1024) {
        int col = i & 63;
        int col2 = ((col & 31) << 1) | (col >> 5);
        sWz[(i & ~63) + col2] = Wz[i];
    }
    for (int i = tid; i < 2064;  i += 1024) sWg[(i >> 3)*12 + (i & 7)] = Wg[i];
    for (int i = tid; i < 258;   i += 1024) { sg[i] = lng[i]; sb[i] = lnb[i]; }
    if (tid < 8) sbg[tid] = bg[tid];

    float xr[6];
    #pragma unroll
    for (int i = 0; i < 6; i++) {
        xr[i] = x[(size_t)n*CIN + lane + 32*i];
        sX[warp*CIN + lane + 32*i] = xr[i];
    }
    float s = 0.f, ss = 0.f;
    #pragma unroll
    for (int i = 0; i < 6; i++) {
        float a = fabsf(xr[i] - xprev[(size_t)n*CIN + lane + 32*i]);
        s += a; ss += a*a;
    }
    #pragma unroll
    for (int o = 16; o; o >>= 1) {
        s  += __shfl_xor_sync(0xffffffffu, s, o);
        ss += __shfl_xor_sync(0xffffffffu, ss, o);
    }
    float dmean = s * (1.0f/192.0f);
    float dvar  = fmaxf((ss - s*dmean) * (1.0f/191.0f), 0.f);
    float mu = log1pf(dmean), sd = log1pf(sqrtf(dvar));

    __syncthreads();

    float z0 = 0.f, z1 = 0.f;
    for (int c = 0; c < CIN; c++) {
        float xv = sX[warp*CIN + c];
        float2 w = *(const float2*)(sWz + c*64 + 2*lane);
        z0 = fmaf(xv, w.x, z0);
        z1 = fmaf(xv, w.y, z1);
    }
    float sa = z0 + z1, s2 = z0*z0 + z1*z1;
    #pragma unroll
    for (int i = 0; i < 6; i++) { sa += xr[i]; s2 += xr[i]*xr[i]; }
    if (lane == 0) { sa += mu + sd; s2 += mu*mu + sd*sd; }
    #pragma unroll
    for (int o = 16; o; o >>= 1) {
        sa += __shfl_xor_sync(0xffffffffu, sa, o);
        s2 += __shfl_xor_sync(0xffffffffu, s2, o);
    }
    float m_   = sa * (1.0f/258.0f);
    float rstd = rsqrtf(s2 * (1.0f/258.0f) - m_*m_ + 1e-5f);

    float acc[8] = {0,0,0,0,0,0,0,0};
    #pragma unroll
    for (int i = 0; i < 6; i++) {
        int idx = lane + 32*i;
        float nv = (xr[i] - m_)*rstd*sg[idx] + sb[idx];
        float4 wa = *(const float4*)(sWg + idx*12);
        float4 wb = *(const float4*)(sWg + idx*12 + 4);
        acc[0]=fmaf(nv,wa.x,acc[0]); acc[1]=fmaf(nv,wa.y,acc[1]);
        acc[2]=fmaf(nv,wa.z,acc[2]); acc[3]=fmaf(nv,wa.w,acc[3]);
        acc[4]=fmaf(nv,wb.x,acc[4]); acc[5]=fmaf(nv,wb.y,acc[5]);
        acc[6]=fmaf(nv,wb.z,acc[6]); acc[7]=fmaf(nv,wb.w,acc[7]);
    }
    {
        int idx = 192 + lane;
        float nv = (z0 - m_)*rstd*sg[idx] + sb[idx];
        float4 wa = *(const float4*)(sWg + idx*12);
        float4 wb = *(const float4*)(sWg + idx*12 + 4);
        acc[0]=fmaf(nv,wa.x,acc[0]); acc[1]=fmaf(nv,wa.y,acc[1]);
        acc[2]=fmaf(nv,wa.z,acc[2]); acc[3]=fmaf(nv,wa.w,acc[3]);
        acc[4]=fmaf(nv,wb.x,acc[4]); acc[5]=fmaf(nv,wb.y,acc[5]);
        acc[6]=fmaf(nv,wb.z,acc[6]); acc[7]=fmaf(nv,wb.w,acc[7]);
        idx = 224 + lane;
        nv = (z1 - m_)*rstd*sg[idx] + sb[idx];
        wa = *(const float4*)(sWg + idx*12);
        wb = *(const float4*)(sWg + idx*12 + 4);
        acc[0]=fmaf(nv,wa.x,acc[0]); acc[1]=fmaf(nv,wa.y,acc[1]);
        acc[2]=fmaf(nv,wa.z,acc[2]); acc[3]=fmaf(nv,wa.w,acc[3]);
        acc[4]=fmaf(nv,wb.x,acc[4]); acc[5]=fmaf(nv,wb.y,acc[5]);
        acc[6]=fmaf(nv,wb.z,acc[6]); acc[7]=fmaf(nv,wb.w,acc[7]);
    }
    if (lane == 0) {
        float nv = (mu - m_)*rstd*sg[256] + sb[256];
        float4 wa = *(const float4*)(sWg + 256*12);
        float4 wb = *(const float4*)(sWg + 256*12 + 4);
        acc[0]=fmaf(nv,wa.x,acc[0]); acc[1]=fmaf(nv,wa.y,acc[1]);
        acc[2]=fmaf(nv,wa.z,acc[2]); acc[3]=fmaf(nv,wa.w,acc[3]);
        acc[4]=fmaf(nv,wb.x,acc[4]); acc[5]=fmaf(nv,wb.y,acc[5]);
        acc[6]=fmaf(nv,wb.z,acc[6]); acc[7]=fmaf(nv,wb.w,acc[7]);
        nv = (sd - m_)*rstd*sg[257] + sb[257];
        wa = *(const float4*)(sWg + 257*12);
        wb = *(const float4*)(sWg + 257*12 + 4);
        acc[0]=fmaf(nv,wa.x,acc[0]); acc[1]=fmaf(nv,wa.y,acc[1]);
        acc[2]=fmaf(nv,wa.z,acc[2]); acc[3]=fmaf(nv,wa.w,acc[3]);
        acc[4]=fmaf(nv,wb.x,acc[4]); acc[5]=fmaf(nv,wb.y,acc[5]);
        acc[6]=fmaf(nv,wb.z,acc[6]); acc[7]=fmaf(nv,wb.w,acc[7]);
    }
    #pragma unroll
    for (int e = 0; e < 8; e++) {
        #pragma unroll
        for (int o = 16; o; o >>= 1) acc[e] += __shfl_xor_sync(0xffffffffu, acc[e], o);
    }
    if (lane == 0) {
        #pragma unroll
        for (int e = 0; e < 8; e++) g_logits[e*NTOK + n] = acc[e] + sbg[e];
        g_mask[n] = 0u;
    }
}

// ---------------- parallel radix select ----------------
__device__ __forceinline__ unsigned f2key(float f) {
    unsigned u = __float_as_uint(f);
    return (u & 0x80000000u) ? ~u : (u | 0x80000000u);
}

__global__ void __launch_bounds__(256) hist_kernel(int shift) {
    __shared__ unsigned hist[256];
    int e = blockIdx.y, tid = threadIdx.x, lane = tid & 31;
    hist[tid] = 0;
    __syncthreads();
    unsigned pmask = (shift == 24) ? 0u : (0xFFFFFFFFu << (shift + 8));
    unsigned prefix = g_thr[e] & pmask;
    const float* base = g_logits + (size_t)e * NTOK;
    int n0 = blockIdx.x * 2048;
    for (int i = tid; i < 2048; i += 256) {
        unsigned k = f2key(base[n0 + i]);
        bool act = ((k & pmask) == prefix);
        unsigned dg = act ? ((k >> shift) & 255u) : 0xffffffffu;
        unsigned peers = __match_any_sync(0xffffffffu, dg);
        if (act && (__ffs(peers) - 1) == lane)
            atomicAdd(&hist[dg], (unsigned)__popc(peers));
    }
    __syncthreads();
    if (hist[tid]) atomicAdd(&g_hist[e][tid], hist[tid]);
}

__global__ void __launch_bounds__(32) digit_kernel(int shift) {
    int e = blockIdx.x, lane = threadIdx.x;
    unsigned need = g_need[e];
    unsigned v[8];
    unsigned lsum = 0;
    #pragma unroll
    for (int j = 0; j < 8; j++) {
        v[j] = g_hist[e][255 - (lane*8 + j)];
        lsum += v[j];
    }
    unsigned inc = lsum;
    #pragma unroll
    for (int o = 1; o < 32; o <<= 1) {
        unsigned t = __shfl_up_sync(0xffffffffu, inc, o);
        if (lane >= o) inc += t;
    }
    unsigned pre = inc - lsum;
    bool crossing = (pre < need) && (pre + lsum >= need);
    if (crossing) {
        unsigned cum = pre;
        #pragma unroll
        for (int j = 0; j < 8; j++) {
            int d = 255 - (lane*8 + j);
            if (d == 0 || cum + v[j] >= need) {
                g_thr[e] |= ((unsigned)d) << shift;
                g_need[e] = need - cum;
                break;
            }
            cum += v[j];
        }
    }
    __syncwarp();
    #pragma unroll
    for (int j = 0; j < 8; j++) g_hist[e][lane*8 + j] = 0u;
}

__global__ void __launch_bounds__(256) mark_kernel() {
    int e = blockIdx.y, c = blockIdx.x, tid = threadIdx.x, lane = tid & 31;
    unsigned thr = g_thr[e];
    const float* base = g_logits + (size_t)e * NTOK;
    int cnt = 0;
    for (int i = tid; i < 1024; i += 256) {
        unsigned k = f2key(base[c*1024 + i]);
        if (k > thr) atomicOr(&g_mask[c*1024 + i], 1u << e);
        cnt += (k == thr);
    }
    #pragma unroll
    for (int o = 16; o; o >>= 1) cnt += __shfl_xor_sync(0xffffffffu, cnt, o);
    __shared__ int ws[8];
    if (lane == 0) ws[tid >> 5] = cnt;
    __syncthreads();
    if (tid == 0) {
        int t = 0;
        for (int w = 0; w < 8; w++) t += ws[w];
        g_ccount[e][c] = t;
    }
}

__global__ void __launch_bounds__(32) scan_kernel() {
    int e = blockIdx.x;
    if (threadIdx.x == 0) {
        int run = 0;
        for (int c = 0; c < 64; c++) { g_cbase[e][c] = run; run += g_ccount[e][c]; }
    }
}

__global__ void __launch_bounds__(32) tie_kernel() {
    int e = blockIdx.y, c = blockIdx.x, lane = threadIdx.x;
    int r = (int)g_need[e];
    int rank = g_cbase[e][c];
    if (rank >= r) return;
    unsigned thr = g_thr[e];
    const float* base = g_logits + (size_t)e * NTOK;
    for (int s = 0; s < 32; s++) {
        int n = c*1024 + s*32 + lane;
        bool p = (f2key(base[n]) == thr);
        unsigned bal = __ballot_sync(0xffffffffu, p);
        int myrank = rank + __popc(bal & ((1u << lane) - 1u));
        if (p && myrank < r) atomicOr(&g_mask[n], 1u << e);
        rank += __popc(bal);
        if (rank >= r) break;
    }
}

// ---------------- routing (block-aggregated dispatch) ----------------
__global__ void __launch_bounds__(256) route_kernel(float* __restrict__ out) {
    __shared__ int sCnt[8], sBase[8];
    int tid = threadIdx.x;
    int n = blockIdx.x * 256 + tid;
    if (tid < 8) sCnt[tid] = 0;
    __syncthreads();

    float l[8];
    #pragma unroll
    for (int e = 0; e < 8; e++) l[e] = g_logits[e*NTOK + n];
    unsigned m = g_mask[n];
    if (m == 0u) {
        int best = 0; float bv = l[0];
        #pragma unroll
        for (int e = 1; e < 8; e++) if (l[e] > bv) { bv = l[e]; best = e; }
        m = 1u << best;
    }
    int e0 = -1, e1 = -1; float v0 = -INFINITY, v1 = -INFINITY;
    #pragma unroll
    for (int e = 0; e < 8; e++) {
        if ((m >> e) & 1u) {
            float f = l[e];
            if (f > v0)      { v1 = v0; e1 = e0; v0 = f; e0 = e; }
            else if (f > v1) { v1 = f; e1 = e; }
        }
    }
    float w0 = 1.f, w1 = 0.f;
    if (e1 >= 0) {
        float ex = expf(v1 - v0);
        w0 = 1.0f / (1.0f + ex);
        w1 = ex * w0;
    }
    bool has1 = (e1 >= 0 && w1 > 0.f);
    int p0 = atomicAdd(&sCnt[e0], 1);
    int p1 = has1 ? atomicAdd(&sCnt[e1], 1) : -1;
    __syncthreads();
    if (tid < 8) sBase[tid] = atomicAdd(&g_cnt[tid], sCnt[tid]);
    __syncthreads();
    {
        int pos = sBase[e0] + p0;
        g_list[e0*NTOK + pos] = n;
        g_wl[e0*NTOK + pos]   = w0;
    }
    unsigned te = (unsigned)e0 | (255u << 8);
    float tw1 = 0.f;
    if (has1) {
        int pos = sBase[e1] + p1;
        g_list[e1*NTOK + pos] = n;
        g_wl[e1*NTOK + pos]   = w1;
        te = (unsigned)e0 | ((unsigned)e1 << 8);
        tw1 = w1;
    }
    g_te[n] = te; g_tw0[n] = w0; g_tw1[n] = tw1;

    float4 z4 = make_float4(0.f, 0.f, 0.f, 0.f);
    float4* o4 = (float4*)out;
    for (int i = n; i < NTOK*OUTD/4; i += NTOK) o4[i] = z4;
}

// ---------------- fused expert FFN v17: coalesced uint2 fragments ------------
__global__ void __launch_bounds__(256, 2) ffn_kernel(
    const float* __restrict__ x,  const float* __restrict__ bw,
    const float* __restrict__ b1, const float* __restrict__ b2,
    float* __restrict__ out)
{
    extern __shared__ float sm[];
    unsigned* um = (unsigned*)sm;
    float* sBw = sm + OFF_BW;
    float* sGw = sm + OFF_GW;
    int*   sTok = (int*)(sm + OFF_TOK);

    int e = blockIdx.y;
    int cnt = g_cnt[e];
    int t0 = blockIdx.x * TTILE;
    if (t0 >= cnt) return;
    int nt = min(TTILE, cnt - t0);
    int tid = threadIdx.x;

    if (tid < TTILE) {
        int idx = t0 + min(tid, nt - 1);
        int tok = g_list[e*NTOK + idx];
        sTok[tid] = tok;
        sGw[tid]  = (tid < nt) ? g_wl[e*NTOK + idx] : 0.f;
        *(float4*)(sBw + tid*4) = *(const float4*)(bw + (size_t)tok*4);
    }
    __syncthreads();

    {   // gather x -> pair-interleaved packed bf16 hi/lo planes [tok][perm(p)]
        int t = tid & 31, part = tid >> 5;
        int tok = sTok[t];
        const float4* src = (const float4*)(x + (size_t)tok*CIN) + part*6;
        #pragma unroll
        for (int i = 0; i < 6; i++) {
            float4 v = src[i];
            unsigned short h0,l0,h1,l1,h2,l2,h3,l3;
            bfsplit(v.x,h0,l0); bfsplit(v.y,h1,l1);
            bfsplit(v.z,h2,l2); bfsplit(v.w,h3,l3);
            int p0 = part*12 + 2*i;
            int o0 = permp(p0), o1 = permp(p0 + 1);
            um[t*XW32 + o0]          = (unsigned)h0 | ((unsigned)h1 << 16);
            um[t*XW32 + o1]          = (unsigned)h2 | ((unsigned)h3 << 16);
            um[OFF_XL + t*XW32 + o0] = (unsigned)l0 | ((unsigned)l1 << 16);
            um[OFF_XL + t*XW32 + o1] = (unsigned)l2 | ((unsigned)l3 << 16);
        }
    }
    __syncthreads();

    int warp = tid >> 5, lane = tid & 31;
    int g = lane >> 2, kq = lane & 3;

    // LoRA1 as MMA: [32,192]x[192,32]
    {
        int mt = warp >> 2, nh = warp & 3;
        float d[4] = {0,0,0,0};
        const unsigned* a1h = g_a1h + (size_t)e*A1PE;
        const unsigned* a1l = g_a1l + (size_t)e*A1PE;
        int rowA = mt*16 + g;
        #pragma unroll
        for (int kt = 0; kt < 12; kt++) {
            unsigned ah[4], al[4];
            int b0 = rowA*XW32 + kt*8 + 2*kq;
            ld64s(um + b0,            ah[0], ah[2]);
            ld64s(um + b0 + 8*XW32,   ah[1], ah[3]);
            ld64s(um + OFF_XL + b0,          al[0], al[2]);
            ld64s(um + OFF_XL + b0 + 8*XW32, al[1], al[3]);
            int wi = ((kt*4 + kq)*32 + nh*8 + g)*2;
            uint2 bh = *(const uint2*)(a1h + wi);
            uint2 bl = *(const uint2*)(a1l + wi);
            mma16(d, ah, bh.x, bh.y);
            mma16(d, ah, bl.x, bl.y);
            mma16(d, al, bh.x, bh.y);
        }
        int off = (12 + (nh >> 1))*8 + 2*kq + (nh & 1);
        #pragma unroll
        for (int half = 0; half < 2; half++) {
            int t = mt*16 + g + half*8;
            float scl = LSCALE * sBw[t*4 + nh];
            unsigned short h0,l0,h1,l1;
            bfsplit(scl*d[2*half],   h0, l0);
            bfsplit(scl*d[2*half+1], h1, l1);
            um[t*XW32 + off]          = (unsigned)h0 | ((unsigned)h1 << 16);
            um[OFF_XL + t*XW32 + off] = (unsigned)l0 | ((unsigned)l1 << 16);
        }
    }
    __syncthreads();

    // ---- layer 1: [32,224]x[224,384]; warp = 2 M-tiles x 48 cols ----
    float d1[2][6][4];
    #pragma unroll
    for (int nj = 0; nj < 6; nj++) {
        int col = warp*48 + nj*8 + 2*kq;
        float b0v = b1[e*HID + col], b1v = b1[e*HID + col + 1];
        #pragma unroll
        for (int mt = 0; mt < 2; mt++) {
            d1[mt][nj][0] = b0v; d1[mt][nj][1] = b1v;
            d1[mt][nj][2] = b0v; d1[mt][nj][3] = b1v;
        }
    }
    const unsigned* w1h = g_w1h + (size_t)e*W1PE;
    const unsigned* w1l = g_w1l + (size_t)e*W1PE;
    for (int kt = 0; kt < 14; kt++) {
        unsigned ah[2][4], al[2][4];
        #pragma unroll
        for (int mt = 0; mt < 2; mt++) {
            int b0 = (mt*16 + g)*XW32 + kt*8 + 2*kq;
            ld64s(um + b0,            ah[mt][0], ah[mt][2]);
            ld64s(um + b0 + 8*XW32,   ah[mt][1], ah[mt][3]);
            ld64s(um + OFF_XL + b0,          al[mt][0], al[mt][2]);
            ld64s(um + OFF_XL + b0 + 8*XW32, al[mt][1], al[mt][3]);
        }
        const unsigned* Wh = w1h + ((kt*4 + kq)*384 + warp*48)*2;
        const unsigned* Wl = w1l + ((kt*4 + kq)*384 + warp*48)*2;
        #pragma unroll
        for (int nj = 0; nj < 6; nj++) {
            uint2 H = *(const uint2*)(Wh + (nj*8 + g)*2);
            uint2 L = *(const uint2*)(Wl + (nj*8 + g)*2);
            #pragma unroll
            for (int mt = 0; mt < 2; mt++) {
                mma16(d1[mt][nj], ah[mt], H.x, H.y);
                mma16(d1[mt][nj], ah[mt], L.x, L.y);
                mma16(d1[mt][nj], al[mt], H.x, H.y);
            }
        }
    }
    __syncthreads();   // X reads done; H overwrites the union region

    // exact GELU -> pair-interleaved packed bf16 split H
    #pragma unroll
    for (int mt = 0; mt < 2; mt++)
        #pragma unroll
        for (int nj = 0; nj < 6; nj++) {
            int off = (3*warp + (nj >> 1))*8 + 2*kq + (nj & 1);
            #pragma unroll
            for (int half = 0; half < 2; half++) {
                int t = mt*16 + g + half*8;
                float v0 = d1[mt][nj][2*half], v1 = d1[mt][nj][2*half + 1];
                float g0 = v0 * 0.5f * (1.0f + erff(v0 * 0.70710678118654752f));
                float g1 = v1 * 0.5f * (1.0f + erff(v1 * 0.70710678118654752f));
                unsigned short h0,l0,h1,l1;
                bfsplit(g0,h0,l0); bfsplit(g1,h1,l1);
                um[t*HW32 + off]          = (unsigned)h0 | ((unsigned)h1 << 16);
                um[OFF_HL + t*HW32 + off] = (unsigned)l0 | ((unsigned)l1 << 16);
            }
        }
    __syncthreads();

    // LoRA2 as MMA: [32,384]x[384,32]
    {
        int mt = warp >> 2, nh = warp & 3;
        float d[4] = {0,0,0,0};
        const unsigned* a2h = g_a2h + (size_t)e*A2PE;
        const unsigned* a2l = g_a2l + (size_t)e*A2PE;
        int rowA = mt*16 + g;
        #pragma unroll 4
        for (int kt = 0; kt < 24; kt++) {
            unsigned ah[4], al[4];
            int b0 = rowA*HW32 + kt*8 + 2*kq;
            ld64s(um + b0,            ah[0], ah[2]);
            ld64s(um + b0 + 8*HW32,   ah[1], ah[3]);
            ld64s(um + OFF_HL + b0,          al[0], al[2]);
            ld64s(um + OFF_HL + b0 + 8*HW32, al[1], al[3]);
            int wi = ((kt*4 + kq)*32 + nh*8 + g)*2;
            uint2 bh = *(const uint2*)(a2h + wi);
            uint2 bl = *(const uint2*)(a2l + wi);
            mma16(d, ah, bh.x, bh.y);
            mma16(d, ah, bl.x, bl.y);
            mma16(d, al, bh.x, bh.y);
        }
        int off = (24 + (nh >> 1))*8 + 2*kq + (nh & 1);
        #pragma unroll
        for (int half = 0; half < 2; half++) {
            int t = mt*16 + g + half*8;
            float scl = LSCALE * sBw[t*4 + nh];
            unsigned short h0,l0,h1,l1;
            bfsplit(scl*d[2*half],   h0, l0);
            bfsplit(scl*d[2*half+1], h1, l1);
            um[t*HW32 + off]          = (unsigned)h0 | ((unsigned)h1 << 16);
            um[OFF_HL + t*HW32 + off] = (unsigned)l0 | ((unsigned)l1 << 16);
        }
    }
    __syncthreads();

    // ---- layer 2: [32,416]x[416,192]; warp = 2 M-tiles x 24 cols ----
    float d2[2][3][4];
    #pragma unroll
    for (int nj = 0; nj < 3; nj++) {
        int col = warp*24 + nj*8 + 2*kq;
        float b0v = b2[e*OUTD + col], b1v = b2[e*OUTD + col + 1];
        #pragma unroll
        for (int mt = 0; mt < 2; mt++) {
            d2[mt][nj][0] = b0v; d2[mt][nj][1] = b1v;
            d2[mt][nj][2] = b0v; d2[mt][nj][3] = b1v;
        }
    }
    const unsigned* w2h = g_w2h + (size_t)e*W2PE;
    const unsigned* w2l = g_w2l + (size_t)e*W2PE;
    for (int kt = 0; kt < 26; kt++) {
        unsigned ah[2][4], al[2][4];
        #pragma unroll
        for (int mt = 0; mt < 2; mt++) {
            int b0 = (mt*16 + g)*HW32 + kt*8 + 2*kq;
            ld64s(um + b0,            ah[mt][0], ah[mt][2]);
            ld64s(um + b0 + 8*HW32,   ah[mt][1], ah[mt][3]);
            ld64s(um + OFF_HL + b0,          al[mt][0], al[mt][2]);
            ld64s(um + OFF_HL + b0 + 8*HW32, al[mt][1], al[mt][3]);
        }
        const unsigned* Wh = w2h + ((kt*4 + kq)*192 + warp*24)*2;
        const unsigned* Wl = w2l + ((kt*4 + kq)*192 + warp*24)*2;
        #pragma unroll
        for (int nj = 0; nj < 3; nj++) {
            uint2 H = *(const uint2*)(Wh + (nj*8 + g)*2);
            uint2 L = *(const uint2*)(Wl + (nj*8 + g)*2);
            #pragma unroll
            for (int mt = 0; mt < 2; mt++) {
                mma16(d2[mt][nj], ah[mt], H.x, H.y);
                mma16(d2[mt][nj], ah[mt], L.x, L.y);
                mma16(d2[mt][nj], al[mt], H.x, H.y);
            }
        }
    }
    // epilogue
    #pragma unroll
    for (int mt = 0; mt < 2; mt++)
        #pragma unroll
        for (int nj = 0; nj < 3; nj++) {
            int col = warp*24 + nj*8 + 2*kq;
            #pragma unroll
            for (int q = 0; q < 4; q++) {
                int t = mt*16 + g + (q >> 1)*8;
                if (t < nt) {
                    int tok = sTok[t];
                    atomicAdd(&out[(size_t)tok*OUTD + col + (q & 1)],
                              sGw[t]*d2[mt][nj][q]);
                }
            }
        }
}

// ---------------- deterministic loss ----------------
__global__ void __launch_bounds__(1024) loss_kernel(float* out, int out_size) {
    __shared__ float sI[8][32], sL[8][32];
    int tid = threadIdx.x, lane = tid & 31, warp = tid >> 5;
    float imp[8] = {0,0,0,0,0,0,0,0}, ld[8] = {0,0,0,0,0,0,0,0};
    for (int n = tid; n < NTOK; n += 1024) {
        unsigned te = g_te[n];
        int e0 = te & 255u, e1 = (te >> 8) & 255u;
        imp[e0] += g_tw0[n]; ld[e0] += 1.f;
        if (e1 != 255) { imp[e1] += g_tw1[n]; ld[e1] += 1.f; }
    }
    #pragma unroll
    for (int e = 0; e < 8; e++) {
        #pragma unroll
        for (int o = 16; o; o >>= 1) {
            imp[e] += __shfl_xor_sync(0xffffffffu, imp[e], o);
            ld[e]  += __shfl_xor_sync(0xffffffffu, ld[e],  o);
        }
        if (lane == 0) { sI[e][warp] = imp[e]; sL[e][warp] = ld[e]; }
    }
    __syncthreads();
    if (tid == 0) {
        float I[8], L[8], mi = 0.f, ml = 0.f;
        for (int e = 0; e < 8; e++) {
            float a = 0.f, b = 0.f;
            for (int w = 0; w < 32; w++) { a += sI[e][w]; b += sL[e][w]; }
            I[e] = a; L[e] = b; mi += a; ml += b;
        }
        mi *= 0.125f; ml *= 0.125f;
        float vi = 0.f, vl = 0.f;
        for (int e = 0; e < 8; e++) {
            float di = I[e] - mi; vi += di*di;
            float dl = L[e] - ml; vl += dl*dl;
        }
        vi *= 0.125f; vl *= 0.125f;
        float loss = (vi / (mi*mi + 1e-10f) + vl / (ml*ml + 1e-10f)) * 0.01f;
        if (out_size > NTOK*OUTD) out[NTOK*OUTD] = loss;
    }
    for (int i = NTOK*OUTD + 1 + tid; i < out_size; i += 1024) out[i] = 0.f;
}

// ---------------- launch ----------------
extern "C" void kernel_launch(void* const* d_in, const int* in_sizes, int n_in,
                              void* d_out, int out_size) {
    const float* x     = (const float*)d_in[0];
    const float* bw    = (const float*)d_in[1];
    const float* xprev = (const float*)d_in[2];
    const float* Wz    = (const float*)d_in[3];
    const float* lng   = (const float*)d_in[4];
    const float* lnb   = (const float*)d_in[5];
    const float* Wg    = (const float*)d_in[6];
    const float* bg    = (const float*)d_in[7];
    const float* W1    = (const float*)d_in[8];
    const float* b1    = (const float*)d_in[9];
    const float* W2    = (const float*)d_in[10];
    const float* b2    = (const float*)d_in[11];
    const float* A1    = (const float*)d_in[12];
    const float* B1    = (const float*)d_in[13];
    const float* A2    = (const float*)d_in[14];
    const float* B2    = (const float*)d_in[15];
    float* out = (float*)d_out;

    const size_t GATE_SMEM = (size_t)(12288 + 3096 + 258 + 258 + 8 + 32*192) * 4;
    const size_t FFN_SMEM  = (size_t)FFN_U32 * 4;
    cudaFuncSetAttribute(gate_kernel, cudaFuncAttributeMaxDynamicSharedMemorySize, (int)GATE_SMEM);
    cudaFuncSetAttribute(ffn_kernel,  cudaFuncAttributeMaxDynamicSharedMemorySize, (int)FFN_SMEM);

    init_kernel<<<2, 1024>>>();
    split_kernel<<<336, 1024>>>(W1, B1, W2, B2, A1, A2);
    gate_kernel<<<NTOK/32, 1024, GATE_SMEM>>>(x, xprev, Wz, lng, lnb, Wg, bg);
    for (int p = 0; p < 4; p++) {
        int shift = 24 - p*8;
        hist_kernel<<<dim3(32, NE), 256>>>(shift);
        digit_kernel<<<NE, 32>>>(shift);
    }
    mark_kernel<<<dim3(64, NE), 256>>>();
    scan_kernel<<<NE, 32>>>();
    tie_kernel<<<dim3(64, NE), 32>>>();
    route_kernel<<<NTOK/256, 256>>>(out);
    ffn_kernel<<<dim3(NTOK/TTILE, NE), 256, FFN_SMEM>>>(x, bw, b1, b2, out);
    loss_kernel<<<1, 1024>>>(out, out_size);
}